// round 17
// baseline (speedup 1.0000x reference)
#include <cuda_runtime.h>
#include <math.h>
#include <stdint.h>

#define BB 32
#define SS 2048
#define KK 512
#define VV 512
#define HH 256
#define MT (SS*BB)      // 65536 rows (row = s*BB + b)
#define SCH 64          // s-chunks for weighted-sum split
#define SPER (SS/SCH)   // 32

// scratch (static device arrays — no allocation allowed)
__device__ float g_hq2[BB*HH];            // q@Wq + bq + bk, [b][h]
__device__ float g_logit[MT];             // logit[s*BB + b]
__device__ float g_partial[SCH*BB*VV];    // split-S partial weighted sums (4MB)

__device__ __forceinline__ uint32_t f2tf32(float f) {
    uint32_t r;
    asm("cvt.rna.tf32.f32 %0, %1;" : "=r"(r) : "f"(f));
    return r;
}

#define MMA_TF32(d, a, b)                                                       \
    asm volatile("mma.sync.aligned.m16n8k8.row.col.f32.tf32.tf32.f32 "          \
                 "{%0,%1,%2,%3}, {%4,%5,%6,%7}, {%8,%9}, {%0,%1,%2,%3};"        \
                 : "+f"(d[0]), "+f"(d[1]), "+f"(d[2]), "+f"(d[3])               \
                 : "r"(a[0]), "r"(a[1]), "r"(a[2]), "r"(a[3]),                  \
                   "r"(b[0]), "r"(b[1]))

// ---------------------------------------------------------------------------
// Kernel 1: hq2[b][h] = q[b]·Wq[h] + bq[h] + bk[h]   (grid BB x 8, 256 thr)
// ---------------------------------------------------------------------------
__global__ void hq_kernel(const float* __restrict__ q, const float* __restrict__ Wq,
                          const float* __restrict__ bq, const float* __restrict__ bk) {
    int b = blockIdx.x;
    int h = blockIdx.y * 32 + (threadIdx.x >> 3);
    int seg = threadIdx.x & 7;             // 64-elem segment of K
    const float4* qp = (const float4*)(q + b*KK + seg*64);
    const float4* wp = (const float4*)(Wq + (size_t)h*KK + seg*64);
    float acc = 0.f;
    #pragma unroll
    for (int i = 0; i < 16; i++) {
        float4 qv = qp[i], wv = wp[i];
        acc += qv.x*wv.x + qv.y*wv.y + qv.z*wv.z + qv.w*wv.w;
    }
    acc += __shfl_xor_sync(0xffffffffu, acc, 1);
    acc += __shfl_xor_sync(0xffffffffu, acc, 2);
    acc += __shfl_xor_sync(0xffffffffu, acc, 4);
    if (seg == 0) g_hq2[b*HH + h] = acc + bq[h] + bk[h];
}

// ---------------------------------------------------------------------------
// Kernel 2: HYBRID tensor+FFMA GEMM + tanh + Wo reduce -> logit[row]
// Staging/layout identical to the proven R5 kernel (tf32 bits in As/Bs).
//   warps 0..11 (tensor): warp grid wm=warp&3 (M), wn=warp>>2 (N 0..2),
//                         cols 0..191 via m16n8k8 tf32 mma.
//   warps 12..15 (FFMA):  cols 192..255 read from the SAME Bs (tf32 bits are
//                         valid floats), rows (warp-12)*32..+31.
// FFMA accumulators alias acc[2][8][4] via accF(i,j) = acc[i&1][j][i>>1].
// ---------------------------------------------------------------------------
#define AS_STR 20
#define BS_STR 264
#define NK_TILES (KK/16)
#define LOGIT_SMEM ((2*128*AS_STR + 2*16*BS_STR)*4 + HH*4 + 128*4*4)

__global__ __launch_bounds__(512, 1) void logit_kernel(
    const float* __restrict__ kmat, const float* __restrict__ Wk,
    const float* __restrict__ Wo,   const float* __restrict__ bo) {
    extern __shared__ char smem_raw[];
    uint32_t* AsBuf[2];
    uint32_t* BsBuf[2];
    AsBuf[0] = (uint32_t*)smem_raw;
    AsBuf[1] = AsBuf[0] + 128*AS_STR;
    BsBuf[0] = AsBuf[1] + 128*AS_STR;
    BsBuf[1] = BsBuf[0] + 16*BS_STR;
    float* wos = (float*)(BsBuf[1] + 16*BS_STR);    // [HH]
    float* red = wos + HH;                           // [128][4]

    const int tid  = threadIdx.x;
    const int lane = tid & 31;
    const int warp = tid >> 5;
    const int base = blockIdx.x * 128;

    if (tid < HH) wos[tid] = Wo[tid];

    // staging indices (identical to R5)
    const int arow = tid >> 2;             // 0..127
    const int acol = (tid & 3) * 4;        // 0,4,8,12
    const int bh   = tid >> 1;             // 0..255 (h)
    const int bko  = (tid & 1) * 8;        // 0 or 8

    float acc[2][8][4];
    #pragma unroll
    for (int mt = 0; mt < 2; mt++)
        #pragma unroll
        for (int nt = 0; nt < 8; nt++)
            #pragma unroll
            for (int c = 0; c < 4; c++) acc[mt][nt][c] = 0.f;

    const float* apt = kmat + (size_t)(base + arow)*KK + acol;
    const float* bpt = Wk + (size_t)bh*KK + bko;

    // ---- prologue: tile 0 -> regs -> smem buf 0 ----
    float4 av  = *(const float4*)(apt);
    float4 bv0 = *(const float4*)(bpt);
    float4 bv1 = *(const float4*)(bpt + 4);
    {
        uint32_t* As = AsBuf[0];
        uint32_t* Bs = BsBuf[0];
        uint4 at;
        at.x = f2tf32(av.x); at.y = f2tf32(av.y);
        at.z = f2tf32(av.z); at.w = f2tf32(av.w);
        *(uint4*)&As[arow*AS_STR + acol] = at;
        Bs[(bko+0)*BS_STR + bh] = f2tf32(bv0.x);
        Bs[(bko+1)*BS_STR + bh] = f2tf32(bv0.y);
        Bs[(bko+2)*BS_STR + bh] = f2tf32(bv0.z);
        Bs[(bko+3)*BS_STR + bh] = f2tf32(bv0.w);
        Bs[(bko+4)*BS_STR + bh] = f2tf32(bv1.x);
        Bs[(bko+5)*BS_STR + bh] = f2tf32(bv1.y);
        Bs[(bko+6)*BS_STR + bh] = f2tf32(bv1.z);
        Bs[(bko+7)*BS_STR + bh] = f2tf32(bv1.w);
    }
    __syncthreads();

    // role constants
    const int wm = warp & 3;               // tensor: M group (also SMSP id)
    const int wn = warp >> 2;              // tensor: N group 0..2 (warp < 12)
    const int g  = lane >> 2;
    const int t  = lane & 3;
    const int fw = warp - 12;              // FFMA warp 0..3
    const int ly = lane >> 3;              // FFMA row lane 0..3
    const int lx = lane & 7;               // FFMA col lane 0..7

    for (int it = 0; it < NK_TILES; it++) {
        if (it + 1 < NK_TILES) {
            int kn = (it + 1) * 16;
            av  = *(const float4*)(apt + kn);
            bv0 = *(const float4*)(bpt + kn);
            bv1 = *(const float4*)(bpt + kn + 4);
        }

        const uint32_t* As = AsBuf[it & 1];
        const uint32_t* Bs = BsBuf[it & 1];
        if (warp < 12) {
            // ---- tensor path (R5-identical, wn limited to 0..2) ----
            #pragma unroll
            for (int ks = 0; ks < 2; ks++) {
                const int kk = ks * 8;
                uint32_t afr[2][4];
                #pragma unroll
                for (int mt = 0; mt < 2; mt++) {
                    int r = wm*32 + mt*16;
                    afr[mt][0] = As[(r + g    )*AS_STR + kk + t    ];
                    afr[mt][1] = As[(r + g + 8)*AS_STR + kk + t    ];
                    afr[mt][2] = As[(r + g    )*AS_STR + kk + t + 4];
                    afr[mt][3] = As[(r + g + 8)*AS_STR + kk + t + 4];
                }
                uint32_t bfr[8][2];
                #pragma unroll
                for (int nt = 0; nt < 8; nt++) {
                    int n = wn*64 + nt*8 + g;
                    bfr[nt][0] = Bs[(kk + t    )*BS_STR + n];
                    bfr[nt][1] = Bs[(kk + t + 4)*BS_STR + n];
                }
                #pragma unroll
                for (int mt = 0; mt < 2; mt++)
                    #pragma unroll
                    for (int nt = 0; nt < 8; nt++)
                        MMA_TF32(acc[mt][nt], afr[mt], bfr[nt]);
            }
        } else {
            // ---- FFMA path: rows fw*32 + ly + 4i, cols 192 + lx + 8j ----
            #pragma unroll
            for (int kk = 0; kk < 16; kk++) {
                float a[8], b[8];
                #pragma unroll
                for (int i = 0; i < 8; i++)
                    a[i] = __uint_as_float(As[(fw*32 + ly + 4*i)*AS_STR + kk]);
                #pragma unroll
                for (int j = 0; j < 8; j++)
                    b[j] = __uint_as_float(Bs[kk*BS_STR + 192 + lx + 8*j]);
                #pragma unroll
                for (int i = 0; i < 8; i++)
                    #pragma unroll
                    for (int j = 0; j < 8; j++)
                        acc[i & 1][j][i >> 1] += a[i] * b[j];
            }
        }

        if (it + 1 < NK_TILES) {
            uint32_t* Asn = AsBuf[(it + 1) & 1];
            uint32_t* Bsn = BsBuf[(it + 1) & 1];
            uint4 at;
            at.x = f2tf32(av.x); at.y = f2tf32(av.y);
            at.z = f2tf32(av.z); at.w = f2tf32(av.w);
            *(uint4*)&Asn[arow*AS_STR + acol] = at;
            Bsn[(bko+0)*BS_STR + bh] = f2tf32(bv0.x);
            Bsn[(bko+1)*BS_STR + bh] = f2tf32(bv0.y);
            Bsn[(bko+2)*BS_STR + bh] = f2tf32(bv0.z);
            Bsn[(bko+3)*BS_STR + bh] = f2tf32(bv0.w);
            Bsn[(bko+4)*BS_STR + bh] = f2tf32(bv1.x);
            Bsn[(bko+5)*BS_STR + bh] = f2tf32(bv1.y);
            Bsn[(bko+6)*BS_STR + bh] = f2tf32(bv1.z);
            Bsn[(bko+7)*BS_STR + bh] = f2tf32(bv1.w);
        }
        __syncthreads();
    }

    // ---- epilogue: tanh + Wo-weighted reduce across H ----
    float bo0 = bo[0];
    if (warp < 12) {
        // C mapping: c0 -> (row g, col 2t), c1 -> (g, 2t+1), c2/c3 -> row g+8
        #pragma unroll
        for (int mt = 0; mt < 2; mt++) {
            #pragma unroll
            for (int rr = 0; rr < 2; rr++) {
                int row_local = wm*32 + mt*16 + rr*8 + g;
                int b = (base + row_local) & (BB - 1);
                const float* hqb = g_hq2 + b*HH;
                float part = 0.f;
                #pragma unroll
                for (int nt = 0; nt < 8; nt++) {
                    int h0 = wn*64 + nt*8 + t*2;
                    float x0 = acc[mt][nt][rr*2+0] + __ldg(hqb + h0);
                    float x1 = acc[mt][nt][rr*2+1] + __ldg(hqb + h0 + 1);
                    part += wos[h0] * tanhf(x0) + wos[h0+1] * tanhf(x1);
                }
                part += __shfl_xor_sync(0xffffffffu, part, 1);
                part += __shfl_xor_sync(0xffffffffu, part, 2);
                if (t == 0) red[row_local*4 + wn] = part;
            }
        }
    } else {
        #pragma unroll
        for (int i = 0; i < 8; i++) {
            int row_local = fw*32 + ly + 4*i;
            int b = (base + row_local) & (BB - 1);
            const float* hqb = g_hq2 + b*HH;
            float part = 0.f;
            #pragma unroll
            for (int j = 0; j < 8; j++) {
                int h = 192 + lx + 8*j;
                part += wos[h] * tanhf(acc[i & 1][j][i >> 1] + __ldg(hqb + h));
            }
            part += __shfl_xor_sync(0xffffffffu, part, 1);
            part += __shfl_xor_sync(0xffffffffu, part, 2);
            part += __shfl_xor_sync(0xffffffffu, part, 4);
            if (lx == 0) red[row_local*4 + 3] = part;
        }
    }
    __syncthreads();
    if (tid < 128)
        g_logit[base + tid] = red[tid*4+0] + red[tid*4+1] + red[tid*4+2] + red[tid*4+3] + bo0;
}

// ---------------------------------------------------------------------------
// Kernel 3: softmax per batch over S; writes final p[b*S+s] into the output.
// ---------------------------------------------------------------------------
__global__ void softmax_kernel(float* __restrict__ p) {
    int b = blockIdx.x, t = threadIdx.x;   // 256 threads
    __shared__ float red[256];
    float m = -3.4e38f;
    for (int s = t; s < SS; s += 256) m = fmaxf(m, g_logit[s*BB + b]);
    red[t] = m; __syncthreads();
    for (int off = 128; off; off >>= 1) {
        if (t < off) red[t] = fmaxf(red[t], red[t + off]);
        __syncthreads();
    }
    m = red[0]; __syncthreads();

    float sum = 0.f;
    for (int s = t; s < SS; s += 256) {
        float e = expf(g_logit[s*BB + b] - m);
        p[b*SS + s] = e;
        sum += e;
    }
    red[t] = sum; __syncthreads();
    for (int off = 128; off; off >>= 1) {
        if (t < off) red[t] += red[t + off];
        __syncthreads();
    }
    float rinv = 1.f / red[0];
    for (int s = t; s < SS; s += 256) p[b*SS + s] *= rinv;
}

// ---------------------------------------------------------------------------
// Kernel 4: partial weighted sum over an s-chunk (float4, smem-staged p):
//   g_partial[sc][b][vc] = sum_{s in chunk} p[b][s] * v[s][b][vc]
// ---------------------------------------------------------------------------
__global__ void wsum_kernel(const float* __restrict__ v, const float* __restrict__ p) {
    int b  = blockIdx.x;
    int sc = blockIdx.y;
    int vc4 = threadIdx.x;   // 128 threads, one float4 each (covers V=512)
    __shared__ float ps[SPER];
    if (threadIdx.x < SPER) ps[threadIdx.x] = p[b*SS + sc*SPER + threadIdx.x];
    __syncthreads();

    const float4* vp = (const float4*)(v + ((size_t)(sc*SPER)*BB + b) * VV) + vc4;
    const size_t stride4 = (size_t)BB * VV / 4;  // float4 stride over s
    float4 acc = make_float4(0.f, 0.f, 0.f, 0.f);
    #pragma unroll 8
    for (int s = 0; s < SPER; s++) {
        float  w = ps[s];
        float4 tv = vp[(size_t)s * stride4];
        acc.x += w * tv.x; acc.y += w * tv.y;
        acc.z += w * tv.z; acc.w += w * tv.w;
    }
    ((float4*)(g_partial + ((size_t)(sc*BB + b)) * VV))[vc4] = acc;
}

// ---------------------------------------------------------------------------
// Kernel 5: reduce split-S partials -> out[b*V + vc]  (deterministic, float4)
// ---------------------------------------------------------------------------
__global__ void reduce_kernel(float* __restrict__ out) {
    int idx4 = blockIdx.x * 256 + threadIdx.x;  // 4096 float4s total
    const float4* gp = (const float4*)g_partial;
    const int stride = BB*VV/4;
    float4 acc = make_float4(0.f, 0.f, 0.f, 0.f);
    #pragma unroll
    for (int c = 0; c < SCH; c++) {
        float4 t = gp[c*stride + idx4];
        acc.x += t.x; acc.y += t.y; acc.z += t.z; acc.w += t.w;
    }
    ((float4*)out)[idx4] = acc;
}

// ---------------------------------------------------------------------------
extern "C" void kernel_launch(void* const* d_in, const int* in_sizes, int n_in,
                              void* d_out, int out_size) {
    const float* q  = (const float*)d_in[0];
    const float* k  = (const float*)d_in[1];
    const float* v  = (const float*)d_in[2];
    const float* Wk = (const float*)d_in[3];
    const float* bk = (const float*)d_in[4];
    const float* Wq = (const float*)d_in[5];
    const float* bq = (const float*)d_in[6];
    const float* Wo = (const float*)d_in[7];
    const float* bo = (const float*)d_in[8];

    float* out = (float*)d_out;          // [1, B, V] -> B*V floats
    float* p   = out + BB*VV;            // [B, S]    -> B*S floats

    static int smem_set = 0;
    if (!smem_set) {
        cudaFuncSetAttribute(logit_kernel,
                             cudaFuncAttributeMaxDynamicSharedMemorySize, LOGIT_SMEM);
        smem_set = 1;
    }

    dim3 g1(BB, 8);
    hq_kernel<<<g1, 256>>>(q, Wq, bq, bk);
    logit_kernel<<<MT/128, 512, LOGIT_SMEM>>>(k, Wk, Wo, bo);
    softmax_kernel<<<BB, 256>>>(p);
    dim3 g4(BB, SCH);
    wsum_kernel<<<g4, 128>>>(v, p);
    reduce_kernel<<<BB*VV/1024, 256>>>(out);
}